// round 11
// baseline (speedup 1.0000x reference)
#include <cuda_runtime.h>
#include <cuda_fp16.h>
#include <math.h>
#include <stdint.h>

#define N_Y   100000
#define N_X   20000
#define KNN   16
#define NE    (N_X * KNN)      // 320000 edges
#define HID   256
#define CIN   64

// Scratch (device globals: allocation-free contract)
__device__ __half  g_Ayh[(size_t)N_Y * HID];   // 51.2 MB (L2-resident)
__device__ __half  g_Bxh[(size_t)N_X * HID];   // 10.2 MB
__device__ __half  g_H2h[(size_t)NE * HID];
// transposed + fp16-converted weights, [n][k] dense
__device__ __half  g_W1aT[256 * 192];
__device__ __half  g_W1bT[256 * 192];
__device__ __half  g_W2T[256 * 256];
__device__ __half  g_W3T[64 * 256];

__device__ __forceinline__ float gelu_f(float v) {
    return 0.5f * v * (1.0f + erff(v * 0.70710678118654752f));
}
__device__ __forceinline__ uint32_t pack_h2(float lo, float hi) {
    __half2 h = __floats2half2_rn(lo, hi);
    return *reinterpret_cast<uint32_t*>(&h);
}
__device__ __forceinline__ void mma_f16(float* d, const uint32_t* a, const uint32_t* b) {
    asm volatile(
        "mma.sync.aligned.m16n8k16.row.col.f32.f16.f16.f32 "
        "{%0,%1,%2,%3}, {%4,%5,%6,%7}, {%8,%9}, {%0,%1,%2,%3};\n"
        : "+f"(d[0]), "+f"(d[1]), "+f"(d[2]), "+f"(d[3])
        : "r"(a[0]), "r"(a[1]), "r"(a[2]), "r"(a[3]), "r"(b[0]), "r"(b[1]));
}
__device__ __forceinline__ void ldsm_x4(uint32_t* r, uint32_t saddr) {
    asm volatile("ldmatrix.sync.aligned.m8n8.x4.shared.b16 {%0,%1,%2,%3}, [%4];"
                 : "=r"(r[0]), "=r"(r[1]), "=r"(r[2]), "=r"(r[3]) : "r"(saddr));
}
__device__ __forceinline__ uint32_t smem_u32(const void* p) {
    return (uint32_t)__cvta_generic_to_shared(p);
}
__device__ __forceinline__ void cpa16(uint32_t dst, const void* src) {
    asm volatile("cp.async.ca.shared.global [%0], [%1], 16;\n" :: "r"(dst), "l"(src));
}
#define CPA_COMMIT asm volatile("cp.async.commit_group;\n")
#define CPA_WAIT0  asm volatile("cp.async.wait_group 0;\n")

// BK=32 fp16 tile: row = 32 halves = 64 B = 4 chunks of 16 B.
// swizzle: chunk' = chunk ^ ((r>>1)&3)
__device__ __forceinline__ uint32_t swb32(int r, int chalf) {   // chalf mult of 8
    return (uint32_t)(r * 64) + (uint32_t)((((chalf >> 3) ^ ((r >> 1) & 3)) << 4));
}
__device__ __forceinline__ uint32_t ldsmA32(uint32_t base, int m0, int kk, int lane) {
    int r = m0 + (lane & 15);
    int ch = (kk >> 3) + (lane >> 4);
    return base + (uint32_t)(r * 64) + (uint32_t)(((ch ^ ((r >> 1) & 3)) << 4));
}
__device__ __forceinline__ uint32_t ldsmB32(uint32_t base, int n0, int kk, int lane) {
    int r = n0 + (lane & 7) + ((lane >> 4) << 3);
    int ch = (kk >> 3) + ((lane >> 3) & 1);
    return base + (uint32_t)(r * 64) + (uint32_t)(((ch ^ ((r >> 1) & 3)) << 4));
}

// ---------------------------------------------------------------------------
// One-launch weight transpose + fp16 convert (fp32 [K][N] -> half [N][K])
// ---------------------------------------------------------------------------
__global__ void transpose_all_kernel(const float* __restrict__ W1,
                                     const float* __restrict__ W2,
                                     const float* __restrict__ W3)
{
    __shared__ float t[32][33];
    int id = blockIdx.x;
    const float* src; __half* dst; int K, N, local;
    if (id < 48)       { src = W1;             dst = g_W1aT; K = 192; N = 256; local = id; }
    else if (id < 96)  { src = W1 + 192 * 256; dst = g_W1bT; K = 192; N = 256; local = id - 48; }
    else if (id < 160) { src = W2;             dst = g_W2T;  K = 256; N = 256; local = id - 96; }
    else               { src = W3;             dst = g_W3T;  K = 256; N = 64;  local = id - 160; }
    int nbx = N / 32;
    int n0 = (local % nbx) * 32, k0 = (local / nbx) * 32;
    int tx = threadIdx.x, ty = threadIdx.y;
#pragma unroll
    for (int i = 0; i < 32; i += 8)
        t[ty + i][tx] = src[(size_t)(k0 + ty + i) * N + n0 + tx];
    __syncthreads();
#pragma unroll
    for (int i = 0; i < 32; i += 8)
        dst[(size_t)(n0 + ty + i) * K + k0 + tx] = __float2half(t[tx][ty + i]);
}

// ---------------------------------------------------------------------------
// Embed + GEMM1: dst[:, nh*128:+128] = emb(pts) @ W[:, half] (+bias)
// BM=128, BN=128 (n-half per CTA), K=192, BK=32, 2-stage.
// 256 threads = 8 warps (4m x 2n), warp tile 32x64. 2 CTAs/SM.
// ---------------------------------------------------------------------------
__global__ void __launch_bounds__(256) embed_mma_kernel(
    const float* __restrict__ pts,
    const float* __restrict__ bias,
    int which, int n)
{
    __shared__ __align__(128) char sA[2 * 128 * 64];   // 16 KB
    __shared__ __align__(128) char sB[2 * 128 * 64];   // 16 KB

    const int nh   = blockIdx.x & 1;
    const int row0 = (blockIdx.x >> 1) * 128;
    const __half* WT = (which ? g_W1bT : g_W1aT) + (size_t)(nh * 128) * 192;
    __half* dst = (which ? g_Bxh : g_Ayh) + nh * 128;
    const int tid  = threadIdx.x;
    const int warp = tid >> 5, lane = tid & 31;
    const int wm = (warp & 3) * 32, wn = (warp >> 2) * 64;
    const int lr = lane >> 2, lc = lane & 3;
    const uint32_t sAu = smem_u32(sA), sBu = smem_u32(sB);

    // hoisted ldmatrix offsets (relative to buffer base)
    uint32_t aOff[2][2], bOff[2][4];
#pragma unroll
    for (int kki = 0; kki < 2; kki++) {
#pragma unroll
        for (int mi = 0; mi < 2; mi++)
            aOff[kki][mi] = ldsmA32(0, wm + mi * 16, kki * 16, lane);
#pragma unroll
        for (int np = 0; np < 4; np++)
            bOff[kki][np] = ldsmB32(0, wn + np * 16, kki * 16, lane);
    }

    // A staging: 2 threads per row, 16 halves each
    const int ar = tid >> 1, cb = (tid & 1) * 16;
    const int arow = row0 + ar;
    float3 p = make_float3(0.f, 0.f, 0.f);
    if (arow < n) { p.x = pts[arow * 3]; p.y = pts[arow * 3 + 1]; p.z = pts[arow * 3 + 2]; }
    // B staging: 2 threads per n-row, 16 halves each
    const int bn = tid >> 1, bw = (tid & 1) * 16;

    auto storeA = [&](int pbuf, int k0) {
        uint32_t w[8];
#pragma unroll
        for (int half = 0; half < 2; half++) {
            int e0e = k0 + cb + half * 8;
            int c = e0e >> 6;
            float pc = c == 0 ? p.x : (c == 1 ? p.y : p.z);
            int fb = (e0e & 63) >> 1;
#pragma unroll
            for (int i = 0; i < 4; i++) {
                float freq = exp2f(-0.41524101186f * (float)(fb + i));
                float s, cf;
                sincosf(pc * freq, &s, &cf);
                w[half * 4 + i] = pack_h2(s, cf);
            }
        }
        *(uint4*)(sA + pbuf * 8192 + swb32(ar, cb))     = make_uint4(w[0], w[1], w[2], w[3]);
        *(uint4*)(sA + pbuf * 8192 + swb32(ar, cb + 8)) = make_uint4(w[4], w[5], w[6], w[7]);
    };
    auto stageB = [&](int k0, int pbuf) {
        char* base = sB + pbuf * 8192;
        cpa16(smem_u32(base + swb32(bn, bw)),     WT + (size_t)bn * 192 + k0 + bw);
        cpa16(smem_u32(base + swb32(bn, bw + 8)), WT + (size_t)bn * 192 + k0 + bw + 8);
        CPA_COMMIT;
    };

    float acc[2][8][4];
#pragma unroll
    for (int mi = 0; mi < 2; mi++)
#pragma unroll
        for (int ni = 0; ni < 8; ni++)
#pragma unroll
            for (int t = 0; t < 4; t++) acc[mi][ni][t] = 0.f;

    storeA(0, 0);
    stageB(0, 0);

    const int NCH = 6;   // 192/32
    for (int i = 0; i < NCH; i++) {
        const int pb = i & 1;
        CPA_WAIT0;
        __syncthreads();
        if (i + 1 < NCH) stageB((i + 1) * 32, 1 - pb);
        const uint32_t aBase = sAu + pb * 8192, bBase = sBu + pb * 8192;
#pragma unroll
        for (int kki = 0; kki < 2; kki++) {
            uint32_t afr[2][4], bfr[4][4];
#pragma unroll
            for (int mi = 0; mi < 2; mi++)
                ldsm_x4(afr[mi], aBase + aOff[kki][mi]);
#pragma unroll
            for (int np = 0; np < 4; np++)
                ldsm_x4(bfr[np], bBase + bOff[kki][np]);
#pragma unroll
            for (int mi = 0; mi < 2; mi++)
#pragma unroll
                for (int np = 0; np < 4; np++) {
                    mma_f16(acc[mi][np * 2],     afr[mi], bfr[np]);
                    mma_f16(acc[mi][np * 2 + 1], afr[mi], bfr[np] + 2);
                }
        }
        if (i + 1 < NCH) storeA(1 - pb, (i + 1) * 32);
    }

    // epilogue: +bias, fp16 store (guarded)
#pragma unroll
    for (int mi = 0; mi < 2; mi++) {
        int r0 = row0 + wm + mi * 16 + lr;
        int r1 = r0 + 8;
#pragma unroll
        for (int ni = 0; ni < 8; ni++) {
            int col = wn + ni * 8 + lc * 2;        // within the n-half
            float bb0 = bias ? bias[nh * 128 + col]     : 0.f;
            float bb1 = bias ? bias[nh * 128 + col + 1] : 0.f;
            if (r0 < n)
                *(uint32_t*)(dst + (size_t)r0 * 256 + col) =
                    pack_h2(acc[mi][ni][0] + bb0, acc[mi][ni][1] + bb1);
            if (r1 < n)
                *(uint32_t*)(dst + (size_t)r1 * 256 + col) =
                    pack_h2(acc[mi][ni][2] + bb0, acc[mi][ni][3] + bb1);
        }
    }
}

// ---------------------------------------------------------------------------
// GEMM2 (fused gather+gelu): H2h[:, nh*128:+128]
//   = h(gelu( gelu(Ayh[nbr]+Bxh[q]) @ W2[:, half] + b2[half] ))
// BM=128 edges, BN=128 (n-half per CTA), K=256, BK=32, 2-stage.
// 256 threads = 8 warps (4m x 2n), warp tile 32x64. 2 CTAs/SM.
// ---------------------------------------------------------------------------
__global__ void __launch_bounds__(256) gemm2_mma_kernel(
    const int*   __restrict__ nbr,
    const float* __restrict__ b2)
{
    __shared__ __align__(128) char sA[2 * 128 * 64];   // 16 KB
    __shared__ __align__(128) char sB[2 * 128 * 64];   // 16 KB

    const int tid  = threadIdx.x;
    const int nh   = blockIdx.x & 1;
    const int e0   = (blockIdx.x >> 1) * 128;
    const int warp = tid >> 5, lane = tid & 31;
    const int wm = (warp & 3) * 32, wn = (warp >> 2) * 64;
    const int lr = lane >> 2, lc = lane & 3;
    const uint32_t sAu = smem_u32(sA), sBu = smem_u32(sB);

    uint32_t aOff[2][2], bOff[2][4];
#pragma unroll
    for (int kki = 0; kki < 2; kki++) {
#pragma unroll
        for (int mi = 0; mi < 2; mi++)
            aOff[kki][mi] = ldsmA32(0, wm + mi * 16, kki * 16, lane);
#pragma unroll
        for (int np = 0; np < 4; np++)
            bOff[kki][np] = ldsmB32(0, wn + np * 16, kki * 16, lane);
    }

    const int ar = tid >> 1, ac = (tid & 1) * 16;
    const int nb = nbr[e0 + ar];
    const __half* pAy = g_Ayh + (size_t)nb * 256 + ac;
    const __half* pBx = g_Bxh + (size_t)((e0 + ar) >> 4) * 256 + ac;
    const int bn = tid >> 1, bw = (tid & 1) * 16;
    const __half* pW = g_W2T + (size_t)(nh * 128 + bn) * 256;

    auto storeA = [&](int pbuf, int k0) {
        uint4 aq0 = *(const uint4*)(pAy + k0);
        uint4 aq1 = *(const uint4*)(pAy + k0 + 8);
        uint4 bq0 = *(const uint4*)(pBx + k0);
        uint4 bq1 = *(const uint4*)(pBx + k0 + 8);
        const __half2* a0 = (const __half2*)&aq0;
        const __half2* a1 = (const __half2*)&aq1;
        const __half2* b0 = (const __half2*)&bq0;
        const __half2* b1 = (const __half2*)&bq1;
        uint32_t w[8];
#pragma unroll
        for (int t = 0; t < 4; t++) {
            float2 af = __half22float2(a0[t]);
            float2 bf = __half22float2(b0[t]);
            w[t] = pack_h2(gelu_f(af.x + bf.x), gelu_f(af.y + bf.y));
            float2 af1 = __half22float2(a1[t]);
            float2 bf1 = __half22float2(b1[t]);
            w[4 + t] = pack_h2(gelu_f(af1.x + bf1.x), gelu_f(af1.y + bf1.y));
        }
        *(uint4*)(sA + pbuf * 8192 + swb32(ar, ac))     = make_uint4(w[0], w[1], w[2], w[3]);
        *(uint4*)(sA + pbuf * 8192 + swb32(ar, ac + 8)) = make_uint4(w[4], w[5], w[6], w[7]);
    };
    auto stageB = [&](int k0, int pbuf) {
        char* base = sB + pbuf * 8192;
        cpa16(smem_u32(base + swb32(bn, bw)),     pW + k0 + bw);
        cpa16(smem_u32(base + swb32(bn, bw + 8)), pW + k0 + bw + 8);
        CPA_COMMIT;
    };

    float acc[2][8][4];
#pragma unroll
    for (int mi = 0; mi < 2; mi++)
#pragma unroll
        for (int ni = 0; ni < 8; ni++)
#pragma unroll
            for (int t = 0; t < 4; t++) acc[mi][ni][t] = 0.f;

    storeA(0, 0);
    stageB(0, 0);

    const int NCH = 8;   // 256/32
    for (int i = 0; i < NCH; i++) {
        const int pb = i & 1;
        CPA_WAIT0;
        __syncthreads();
        if (i + 1 < NCH) stageB((i + 1) * 32, 1 - pb);
        const uint32_t aBase = sAu + pb * 8192, bBase = sBu + pb * 8192;
#pragma unroll
        for (int kki = 0; kki < 2; kki++) {
            uint32_t afr[2][4], bfr[4][4];
#pragma unroll
            for (int mi = 0; mi < 2; mi++)
                ldsm_x4(afr[mi], aBase + aOff[kki][mi]);
#pragma unroll
            for (int np = 0; np < 4; np++)
                ldsm_x4(bfr[np], bBase + bOff[kki][np]);
#pragma unroll
            for (int mi = 0; mi < 2; mi++)
#pragma unroll
                for (int np = 0; np < 4; np++) {
                    mma_f16(acc[mi][np * 2],     afr[mi], bfr[np]);
                    mma_f16(acc[mi][np * 2 + 1], afr[mi], bfr[np] + 2);
                }
        }
        if (i + 1 < NCH) storeA(1 - pb, (i + 1) * 32);
    }

    // epilogue: +b2, gelu, fp16-store into the n-half columns
    __half* dst = g_H2h + nh * 128;
#pragma unroll
    for (int mi = 0; mi < 2; mi++) {
        int r0 = e0 + wm + mi * 16 + lr;
#pragma unroll
        for (int ni = 0; ni < 8; ni++) {
            int col = wn + ni * 8 + lc * 2;
            float bb0 = b2[nh * 128 + col], bb1 = b2[nh * 128 + col + 1];
            *(uint32_t*)(dst + (size_t)r0 * 256 + col) =
                pack_h2(gelu_f(acc[mi][ni][0] + bb0), gelu_f(acc[mi][ni][1] + bb1));
            *(uint32_t*)(dst + (size_t)(r0 + 8) * 256 + col) =
                pack_h2(gelu_f(acc[mi][ni][2] + bb0), gelu_f(acc[mi][ni][3] + bb1));
        }
    }
}

// ---------------------------------------------------------------------------
// GEMM3 + segsum: out = segsum( (H2 @ W3 + b3) * f_y[nbr] )
// BM=128, BN=64, K=256, BK=32, 2-stage. 256 threads = 8 m-warps (m16 x n64).
// ---------------------------------------------------------------------------
__global__ void __launch_bounds__(256) gemm3_mma_kernel(
    const int*   __restrict__ nbr,
    const float* __restrict__ b3,
    const float* __restrict__ fy,
    float*       __restrict__ out)
{
    __shared__ __align__(128) char sA[2 * 128 * 64];
    __shared__ __align__(128) char sB3[2 * 64 * 64];
    __shared__ int s_nbr[128];

    const int tid  = threadIdx.x;
    const int e0   = blockIdx.x * 128;
    const int warp = tid >> 5, lane = tid & 31;
    const int lr = lane >> 2, lc = lane & 3;
    const uint32_t sAu = smem_u32(sA), sBu = smem_u32(sB3);

    if (tid < 128) s_nbr[tid] = nbr[e0 + tid];

    const int ar = tid >> 1, cw = (tid & 1) * 16;
    const __half* pA = g_H2h + (size_t)(e0 + ar) * 256 + cw;
    const int b3n = tid >> 2, b3w = (tid & 3) * 8;

    uint32_t aOff[2], bOff[2][4];
#pragma unroll
    for (int kki = 0; kki < 2; kki++) {
        aOff[kki] = ldsmA32(0, warp * 16, kki * 16, lane);
#pragma unroll
        for (int np = 0; np < 4; np++)
            bOff[kki][np] = ldsmB32(0, np * 16, kki * 16, lane);
    }

    auto stage = [&](int k0, int pbuf) {
        char* abase = sA + pbuf * 8192;
        cpa16(smem_u32(abase + swb32(ar, cw)),     pA + k0);
        cpa16(smem_u32(abase + swb32(ar, cw + 8)), pA + k0 + 8);
        cpa16(smem_u32(sB3 + pbuf * 4096 + swb32(b3n, b3w)),
              g_W3T + (size_t)b3n * 256 + k0 + b3w);
        CPA_COMMIT;
    };

    float acc3[8][4];
#pragma unroll
    for (int ni = 0; ni < 8; ni++)
#pragma unroll
        for (int t = 0; t < 4; t++) acc3[ni][t] = 0.f;

    stage(0, 0);

    const int NCH = 8;
    for (int i = 0; i < NCH; i++) {
        const int pb = i & 1;
        CPA_WAIT0;
        __syncthreads();
        if (i + 1 < NCH) stage((i + 1) * 32, 1 - pb);
        const uint32_t aBase = sAu + pb * 8192, bBase = sBu + pb * 4096;
#pragma unroll
        for (int kki = 0; kki < 2; kki++) {
            uint32_t afr[4], bfr[4][4];
            ldsm_x4(afr, aBase + aOff[kki]);
#pragma unroll
            for (int np = 0; np < 4; np++)
                ldsm_x4(bfr[np], bBase + bOff[kki][np]);
#pragma unroll
            for (int np = 0; np < 4; np++) {
                mma_f16(acc3[np * 2],     afr, bfr[np]);
                mma_f16(acc3[np * 2 + 1], afr, bfr[np] + 2);
            }
        }
    }

    {
        int r0 = warp * 16 + lr;
        int nb0 = s_nbr[r0], nb1 = s_nbr[r0 + 8];
        const int q = blockIdx.x * 8 + warp;
#pragma unroll
        for (int ni = 0; ni < 8; ni++) {
            int col = ni * 8 + lc * 2;
            float bb0 = b3[col], bb1 = b3[col + 1];
            float2 f0 = *(const float2*)(fy + (size_t)nb0 * 64 + col);
            float2 f1 = *(const float2*)(fy + (size_t)nb1 * 64 + col);
            float s0 = (acc3[ni][0] + bb0) * f0.x + (acc3[ni][2] + bb0) * f1.x;
            float s1 = (acc3[ni][1] + bb1) * f0.y + (acc3[ni][3] + bb1) * f1.y;
#pragma unroll
            for (int off = 4; off <= 16; off <<= 1) {
                s0 += __shfl_xor_sync(0xFFFFFFFFu, s0, off);
                s1 += __shfl_xor_sync(0xFFFFFFFFu, s1, off);
            }
            if (lr == 0)
                *(float2*)(out + (size_t)q * 64 + col) = make_float2(s0, s1);
        }
    }
}

// ---------------------------------------------------------------------------
extern "C" void kernel_launch(void* const* d_in, const int* in_sizes, int n_in,
                              void* d_out, int out_size)
{
    const float* y   = (const float*)d_in[0];
    const float* x   = (const float*)d_in[1];
    const float* f_y = (const float*)d_in[2];
    const int*   nbr = (const int*)d_in[3];
    // d_in[4] = neighbors_row_splits (uniform K=16 -> q = e>>4)
    const float* W1  = (const float*)d_in[5];
    const float* b1  = (const float*)d_in[6];
    const float* W2  = (const float*)d_in[7];
    const float* b2  = (const float*)d_in[8];
    const float* W3  = (const float*)d_in[9];
    const float* b3  = (const float*)d_in[10];
    float* out = (float*)d_out;

    transpose_all_kernel<<<176, dim3(32, 8)>>>(W1, W2, W3);
    embed_mma_kernel<<<((N_Y + 127) / 128) * 2, 256>>>(y, nullptr, 0, N_Y);
    embed_mma_kernel<<<((N_X + 127) / 128) * 2, 256>>>(x, b1, 1, N_X);
    gemm2_mma_kernel<<<(NE / 128) * 2, 256>>>(nbr, b2);
    gemm3_mma_kernel<<<NE / 128, 256>>>(nbr, b3, f_y, out);
}

// round 12
// speedup vs baseline: 1.1519x; 1.1519x over previous
#include <cuda_runtime.h>
#include <cuda_fp16.h>
#include <math.h>
#include <stdint.h>

#define N_Y   100000
#define N_X   20000
#define KNN   16
#define NE    (N_X * KNN)      // 320000 edges
#define HID   256
#define CIN   64

// Scratch (device globals: allocation-free contract)
__device__ __half  g_Ayh[(size_t)N_Y * HID];   // 51.2 MB (L2-resident)
__device__ __half  g_Bxh[(size_t)N_X * HID];   // 10.2 MB
__device__ __half  g_H1h[(size_t)NE * HID];    // 164 MB
__device__ __half  g_H2h[(size_t)NE * HID];    // 164 MB
// transposed + fp16-converted weights, [n][k] dense
__device__ __half  g_W1aT[256 * 192];
__device__ __half  g_W1bT[256 * 192];
__device__ __half  g_W2T[256 * 256];
__device__ __half  g_W3T[64 * 256];

__device__ __forceinline__ float gelu_f(float v) {
    return 0.5f * v * (1.0f + erff(v * 0.70710678118654752f));
}
__device__ __forceinline__ uint32_t pack_h2(float lo, float hi) {
    __half2 h = __floats2half2_rn(lo, hi);
    return *reinterpret_cast<uint32_t*>(&h);
}
__device__ __forceinline__ void mma_f16(float* d, const uint32_t* a, const uint32_t* b) {
    asm volatile(
        "mma.sync.aligned.m16n8k16.row.col.f32.f16.f16.f32 "
        "{%0,%1,%2,%3}, {%4,%5,%6,%7}, {%8,%9}, {%0,%1,%2,%3};\n"
        : "+f"(d[0]), "+f"(d[1]), "+f"(d[2]), "+f"(d[3])
        : "r"(a[0]), "r"(a[1]), "r"(a[2]), "r"(a[3]), "r"(b[0]), "r"(b[1]));
}
__device__ __forceinline__ void ldsm_x4(uint32_t* r, uint32_t saddr) {
    asm volatile("ldmatrix.sync.aligned.m8n8.x4.shared.b16 {%0,%1,%2,%3}, [%4];"
                 : "=r"(r[0]), "=r"(r[1]), "=r"(r[2]), "=r"(r[3]) : "r"(saddr));
}
__device__ __forceinline__ uint32_t smem_u32(const void* p) {
    return (uint32_t)__cvta_generic_to_shared(p);
}
__device__ __forceinline__ void cpa16(uint32_t dst, const void* src) {
    asm volatile("cp.async.ca.shared.global [%0], [%1], 16;\n" :: "r"(dst), "l"(src));
}
#define CPA_COMMIT asm volatile("cp.async.commit_group;\n")
#define CPA_WAIT0  asm volatile("cp.async.wait_group 0;\n")

// BK=32 fp16 tile: row = 32 halves = 64 B = 4 chunks of 16 B.
// swizzle: chunk' = chunk ^ ((r>>1)&3)
__device__ __forceinline__ uint32_t swb32(int r, int chalf) {   // chalf mult of 8
    return (uint32_t)(r * 64) + (uint32_t)((((chalf >> 3) ^ ((r >> 1) & 3)) << 4));
}
__device__ __forceinline__ uint32_t ldsmA32(uint32_t base, int m0, int kk, int lane) {
    int r = m0 + (lane & 15);
    int ch = (kk >> 3) + (lane >> 4);
    return base + (uint32_t)(r * 64) + (uint32_t)(((ch ^ ((r >> 1) & 3)) << 4));
}
__device__ __forceinline__ uint32_t ldsmB32(uint32_t base, int n0, int kk, int lane) {
    int r = n0 + (lane & 7) + ((lane >> 4) << 3);
    int ch = (kk >> 3) + ((lane >> 3) & 1);
    return base + (uint32_t)(r * 64) + (uint32_t)(((ch ^ ((r >> 1) & 3)) << 4));
}

// ---------------------------------------------------------------------------
// One-launch weight transpose + fp16 convert (fp32 [K][N] -> half [N][K])
// ---------------------------------------------------------------------------
__global__ void transpose_all_kernel(const float* __restrict__ W1,
                                     const float* __restrict__ W2,
                                     const float* __restrict__ W3)
{
    __shared__ float t[32][33];
    int id = blockIdx.x;
    const float* src; __half* dst; int K, N, local;
    if (id < 48)       { src = W1;             dst = g_W1aT; K = 192; N = 256; local = id; }
    else if (id < 96)  { src = W1 + 192 * 256; dst = g_W1bT; K = 192; N = 256; local = id - 48; }
    else if (id < 160) { src = W2;             dst = g_W2T;  K = 256; N = 256; local = id - 96; }
    else               { src = W3;             dst = g_W3T;  K = 256; N = 64;  local = id - 160; }
    int nbx = N / 32;
    int n0 = (local % nbx) * 32, k0 = (local / nbx) * 32;
    int tx = threadIdx.x, ty = threadIdx.y;
#pragma unroll
    for (int i = 0; i < 32; i += 8)
        t[ty + i][tx] = src[(size_t)(k0 + ty + i) * N + n0 + tx];
    __syncthreads();
#pragma unroll
    for (int i = 0; i < 32; i += 8)
        dst[(size_t)(n0 + ty + i) * K + k0 + tx] = __float2half(t[tx][ty + i]);
}

// ---------------------------------------------------------------------------
// Embed + GEMM1 (mma.sync fp16, R8 form)
// ---------------------------------------------------------------------------
__global__ void __launch_bounds__(512) embed_mma_kernel(
    const float* __restrict__ pts,
    const float* __restrict__ bias,
    int which, int n)
{
    __shared__ __align__(128) char sA[2 * 128 * 64];
    __shared__ __align__(128) char sB[2 * 256 * 64];

    const __half* WT = which ? g_W1bT : g_W1aT;
    __half* dst = which ? g_Bxh : g_Ayh;
    const int tid  = threadIdx.x;
    const int row0 = blockIdx.x * 128;
    const int warp = tid >> 5, lane = tid & 31;
    const int wm = (warp & 3) * 32, wn = (warp >> 2) * 64;
    const int lr = lane >> 2, lc = lane & 3;
    const uint32_t sAu = smem_u32(sA), sBu = smem_u32(sB);

    uint32_t aOff[2][2], bOff[2][4];
#pragma unroll
    for (int kki = 0; kki < 2; kki++) {
#pragma unroll
        for (int mi = 0; mi < 2; mi++)
            aOff[kki][mi] = ldsmA32(0, wm + mi * 16, kki * 16, lane);
#pragma unroll
        for (int np = 0; np < 4; np++)
            bOff[kki][np] = ldsmB32(0, wn + np * 16, kki * 16, lane);
    }

    const int ar = tid >> 2, cb = (tid & 3) * 8;
    const int arow = row0 + ar;
    float3 p = make_float3(0.f, 0.f, 0.f);
    if (arow < n) { p.x = pts[arow * 3]; p.y = pts[arow * 3 + 1]; p.z = pts[arow * 3 + 2]; }
    const int bn = tid >> 1, bw = (tid & 1) * 16;

    auto storeA = [&](int pbuf, int k0) {
        int e0e = k0 + cb;
        int c = e0e >> 6;
        float pc = c == 0 ? p.x : (c == 1 ? p.y : p.z);
        int fb = (e0e & 63) >> 1;
        uint32_t w[4];
#pragma unroll
        for (int i = 0; i < 4; i++) {
            float freq = exp2f(-0.41524101186f * (float)(fb + i));
            float s, cf;
            sincosf(pc * freq, &s, &cf);
            w[i] = pack_h2(s, cf);
        }
        *(uint4*)(sA + pbuf * 8192 + swb32(ar, cb)) = make_uint4(w[0], w[1], w[2], w[3]);
    };
    auto stageB = [&](int k0, int pbuf) {
        char* base = sB + pbuf * 16384;
        cpa16(smem_u32(base + swb32(bn, bw)),     WT + (size_t)bn * 192 + k0 + bw);
        cpa16(smem_u32(base + swb32(bn, bw + 8)), WT + (size_t)bn * 192 + k0 + bw + 8);
        CPA_COMMIT;
    };

    float acc[2][8][4];
#pragma unroll
    for (int mi = 0; mi < 2; mi++)
#pragma unroll
        for (int ni = 0; ni < 8; ni++)
#pragma unroll
            for (int t = 0; t < 4; t++) acc[mi][ni][t] = 0.f;

    storeA(0, 0);
    stageB(0, 0);

    const int NCH = 6;
    for (int i = 0; i < NCH; i++) {
        const int pb = i & 1;
        CPA_WAIT0;
        __syncthreads();
        if (i + 1 < NCH) stageB((i + 1) * 32, 1 - pb);
        const uint32_t aBase = sAu + pb * 8192, bBase = sBu + pb * 16384;
#pragma unroll
        for (int kki = 0; kki < 2; kki++) {
            uint32_t afr[2][4], bfr[4][4];
#pragma unroll
            for (int mi = 0; mi < 2; mi++)
                ldsm_x4(afr[mi], aBase + aOff[kki][mi]);
#pragma unroll
            for (int np = 0; np < 4; np++)
                ldsm_x4(bfr[np], bBase + bOff[kki][np]);
#pragma unroll
            for (int mi = 0; mi < 2; mi++)
#pragma unroll
                for (int np = 0; np < 4; np++) {
                    mma_f16(acc[mi][np * 2],     afr[mi], bfr[np]);
                    mma_f16(acc[mi][np * 2 + 1], afr[mi], bfr[np] + 2);
                }
        }
        if (i + 1 < NCH) storeA(1 - pb, (i + 1) * 32);
    }

#pragma unroll
    for (int mi = 0; mi < 2; mi++) {
        int r0 = row0 + wm + mi * 16 + lr;
        int r1 = r0 + 8;
#pragma unroll
        for (int ni = 0; ni < 8; ni++) {
            int col = wn + ni * 8 + lc * 2;
            float bb0 = bias ? bias[col]     : 0.f;
            float bb1 = bias ? bias[col + 1] : 0.f;
            if (r0 < n)
                *(uint32_t*)(dst + (size_t)r0 * 256 + col) =
                    pack_h2(acc[mi][ni][0] + bb0, acc[mi][ni][1] + bb1);
            if (r1 < n)
                *(uint32_t*)(dst + (size_t)r1 * 256 + col) =
                    pack_h2(acc[mi][ni][2] + bb0, acc[mi][ni][3] + bb1);
        }
    }
}

// ---------------------------------------------------------------------------
// H1 elementwise: H1h[e,:] = fp16(gelu(Ayh[nbr[e],:] + Bxh[e>>4,:]))
// 8 halves/thread; grid*block == NE*32 exactly.
// ---------------------------------------------------------------------------
__global__ void __launch_bounds__(256) h1_kernel(const int* __restrict__ nbr)
{
    int idx = blockIdx.x * 256 + threadIdx.x;   // [0, NE*32)
    int e  = idx >> 5;
    int c8 = (idx & 31) * 8;
    int nb = __ldg(nbr + e);
    int q  = e >> 4;
    uint4 aq = *(const uint4*)(g_Ayh + (size_t)nb * 256 + c8);
    uint4 bq = *(const uint4*)(g_Bxh + (size_t)q  * 256 + c8);
    const __half2* ah = (const __half2*)&aq;
    const __half2* bh = (const __half2*)&bq;
    uint32_t w[4];
#pragma unroll
    for (int t = 0; t < 4; t++) {
        float2 af = __half22float2(ah[t]);
        float2 bf = __half22float2(bh[t]);
        w[t] = pack_h2(gelu_f(af.x + bf.x), gelu_f(af.y + bf.y));
    }
    *(uint4*)(g_H1h + (size_t)e * 256 + c8) = make_uint4(w[0], w[1], w[2], w[3]);
}

// ---------------------------------------------------------------------------
// GEMM2 (pure): H2h = h(gelu( H1h @ W2 + b2 ))
// BM=128, BN=256, K=256, BK=32, 2-stage, all-cp.async staging.
// 512 threads = 16 warps (4m x 4n), warp tile 32x64.
// ---------------------------------------------------------------------------
__global__ void __launch_bounds__(512) gemm2_mma_kernel(const float* __restrict__ b2)
{
    __shared__ __align__(128) char sA[2 * 128 * 64];   // 16 KB
    __shared__ __align__(128) char sB[2 * 256 * 64];   // 32 KB

    const int tid  = threadIdx.x;
    const int e0   = blockIdx.x * 128;
    const int warp = tid >> 5, lane = tid & 31;
    const int wm = (warp & 3) * 32, wn = (warp >> 2) * 64;
    const int lr = lane >> 2, lc = lane & 3;
    const uint32_t sAu = smem_u32(sA), sBu = smem_u32(sB);

    uint32_t aOff[2][2], bOff[2][4];
#pragma unroll
    for (int kki = 0; kki < 2; kki++) {
#pragma unroll
        for (int mi = 0; mi < 2; mi++)
            aOff[kki][mi] = ldsmA32(0, wm + mi * 16, kki * 16, lane);
#pragma unroll
        for (int np = 0; np < 4; np++)
            bOff[kki][np] = ldsmB32(0, wn + np * 16, kki * 16, lane);
    }

    const int ar = tid >> 2, ac = (tid & 3) * 8;       // A: 1 cp.async/thread
    const __half* pH1 = g_H1h + (size_t)(e0 + ar) * 256 + ac;
    const int bn = tid >> 1, bw = (tid & 1) * 16;      // B: 2 cp.async/thread
    const __half* pW = g_W2T + (size_t)bn * 256;

    auto stage = [&](int k0, int pbuf) {
        cpa16(smem_u32(sA + pbuf * 8192 + swb32(ar, ac)), pH1 + k0);
        char* base = sB + pbuf * 16384;
        cpa16(smem_u32(base + swb32(bn, bw)),     pW + k0 + bw);
        cpa16(smem_u32(base + swb32(bn, bw + 8)), pW + k0 + bw + 8);
        CPA_COMMIT;
    };

    float acc[2][8][4];
#pragma unroll
    for (int mi = 0; mi < 2; mi++)
#pragma unroll
        for (int ni = 0; ni < 8; ni++)
#pragma unroll
            for (int t = 0; t < 4; t++) acc[mi][ni][t] = 0.f;

    stage(0, 0);

    const int NCH = 8;   // 256/32
    for (int i = 0; i < NCH; i++) {
        const int pb = i & 1;
        CPA_WAIT0;
        __syncthreads();
        if (i + 1 < NCH) stage((i + 1) * 32, 1 - pb);
        const uint32_t aBase = sAu + pb * 8192, bBase = sBu + pb * 16384;
#pragma unroll
        for (int kki = 0; kki < 2; kki++) {
            uint32_t afr[2][4], bfr[4][4];
#pragma unroll
            for (int mi = 0; mi < 2; mi++)
                ldsm_x4(afr[mi], aBase + aOff[kki][mi]);
#pragma unroll
            for (int np = 0; np < 4; np++)
                ldsm_x4(bfr[np], bBase + bOff[kki][np]);
#pragma unroll
            for (int mi = 0; mi < 2; mi++)
#pragma unroll
                for (int np = 0; np < 4; np++) {
                    mma_f16(acc[mi][np * 2],     afr[mi], bfr[np]);
                    mma_f16(acc[mi][np * 2 + 1], afr[mi], bfr[np] + 2);
                }
        }
    }

    // epilogue: +b2, gelu, fp16-store
#pragma unroll
    for (int mi = 0; mi < 2; mi++) {
        int r0 = e0 + wm + mi * 16 + lr;
#pragma unroll
        for (int ni = 0; ni < 8; ni++) {
            int col = wn + ni * 8 + lc * 2;
            float bb0 = b2[col], bb1 = b2[col + 1];
            *(uint32_t*)(g_H2h + (size_t)r0 * 256 + col) =
                pack_h2(gelu_f(acc[mi][ni][0] + bb0), gelu_f(acc[mi][ni][1] + bb1));
            *(uint32_t*)(g_H2h + (size_t)(r0 + 8) * 256 + col) =
                pack_h2(gelu_f(acc[mi][ni][2] + bb0), gelu_f(acc[mi][ni][3] + bb1));
        }
    }
}

// ---------------------------------------------------------------------------
// GEMM3 + segsum: out = segsum( (H2 @ W3 + b3) * f_y[nbr] )
// BM=128, BN=64, K=256, BK=32, 2-stage. 256 threads = 8 m-warps (m16 x n64).
// ---------------------------------------------------------------------------
__global__ void __launch_bounds__(256) gemm3_mma_kernel(
    const int*   __restrict__ nbr,
    const float* __restrict__ b3,
    const float* __restrict__ fy,
    float*       __restrict__ out)
{
    __shared__ __align__(128) char sA[2 * 128 * 64];
    __shared__ __align__(128) char sB3[2 * 64 * 64];
    __shared__ int s_nbr[128];

    const int tid  = threadIdx.x;
    const int e0   = blockIdx.x * 128;
    const int warp = tid >> 5, lane = tid & 31;
    const int lr = lane >> 2, lc = lane & 3;
    const uint32_t sAu = smem_u32(sA), sBu = smem_u32(sB3);

    if (tid < 128) s_nbr[tid] = nbr[e0 + tid];

    const int ar = tid >> 1, cw = (tid & 1) * 16;
    const __half* pA = g_H2h + (size_t)(e0 + ar) * 256 + cw;
    const int b3n = tid >> 2, b3w = (tid & 3) * 8;

    uint32_t aOff[2], bOff[2][4];
#pragma unroll
    for (int kki = 0; kki < 2; kki++) {
        aOff[kki] = ldsmA32(0, warp * 16, kki * 16, lane);
#pragma unroll
        for (int np = 0; np < 4; np++)
            bOff[kki][np] = ldsmB32(0, np * 16, kki * 16, lane);
    }

    auto stage = [&](int k0, int pbuf) {
        char* abase = sA + pbuf * 8192;
        cpa16(smem_u32(abase + swb32(ar, cw)),     pA + k0);
        cpa16(smem_u32(abase + swb32(ar, cw + 8)), pA + k0 + 8);
        cpa16(smem_u32(sB3 + pbuf * 4096 + swb32(b3n, b3w)),
              g_W3T + (size_t)b3n * 256 + k0 + b3w);
        CPA_COMMIT;
    };

    float acc3[8][4];
#pragma unroll
    for (int ni = 0; ni < 8; ni++)
#pragma unroll
        for (int t = 0; t < 4; t++) acc3[ni][t] = 0.f;

    stage(0, 0);

    const int NCH = 8;
    for (int i = 0; i < NCH; i++) {
        const int pb = i & 1;
        CPA_WAIT0;
        __syncthreads();
        if (i + 1 < NCH) stage((i + 1) * 32, 1 - pb);
        const uint32_t aBase = sAu + pb * 8192, bBase = sBu + pb * 4096;
#pragma unroll
        for (int kki = 0; kki < 2; kki++) {
            uint32_t afr[4], bfr[4][4];
            ldsm_x4(afr, aBase + aOff[kki]);
#pragma unroll
            for (int np = 0; np < 4; np++)
                ldsm_x4(bfr[np], bBase + bOff[kki][np]);
#pragma unroll
            for (int np = 0; np < 4; np++) {
                mma_f16(acc3[np * 2],     afr, bfr[np]);
                mma_f16(acc3[np * 2 + 1], afr, bfr[np] + 2);
            }
        }
    }

    {
        int r0 = warp * 16 + lr;
        int nb0 = s_nbr[r0], nb1 = s_nbr[r0 + 8];
        const int q = blockIdx.x * 8 + warp;
#pragma unroll
        for (int ni = 0; ni < 8; ni++) {
            int col = ni * 8 + lc * 2;
            float bb0 = b3[col], bb1 = b3[col + 1];
            float2 f0 = *(const float2*)(fy + (size_t)nb0 * 64 + col);
            float2 f1 = *(const float2*)(fy + (size_t)nb1 * 64 + col);
            float s0 = (acc3[ni][0] + bb0) * f0.x + (acc3[ni][2] + bb0) * f1.x;
            float s1 = (acc3[ni][1] + bb1) * f0.y + (acc3[ni][3] + bb1) * f1.y;
#pragma unroll
            for (int off = 4; off <= 16; off <<= 1) {
                s0 += __shfl_xor_sync(0xFFFFFFFFu, s0, off);
                s1 += __shfl_xor_sync(0xFFFFFFFFu, s1, off);
            }
            if (lr == 0)
                *(float2*)(out + (size_t)q * 64 + col) = make_float2(s0, s1);
        }
    }
}

// ---------------------------------------------------------------------------
extern "C" void kernel_launch(void* const* d_in, const int* in_sizes, int n_in,
                              void* d_out, int out_size)
{
    const float* y   = (const float*)d_in[0];
    const float* x   = (const float*)d_in[1];
    const float* f_y = (const float*)d_in[2];
    const int*   nbr = (const int*)d_in[3];
    // d_in[4] = neighbors_row_splits (uniform K=16 -> q = e>>4)
    const float* W1  = (const float*)d_in[5];
    const float* b1  = (const float*)d_in[6];
    const float* W2  = (const float*)d_in[7];
    const float* b2  = (const float*)d_in[8];
    const float* W3  = (const float*)d_in[9];
    const float* b3  = (const float*)d_in[10];
    float* out = (float*)d_out;

    transpose_all_kernel<<<176, dim3(32, 8)>>>(W1, W2, W3);
    embed_mma_kernel<<<(N_Y + 127) / 128, 512>>>(y, nullptr, 0, N_Y);
    embed_mma_kernel<<<(N_X + 127) / 128, 512>>>(x, b1, 1, N_X);
    h1_kernel<<<(NE * 32) / 256, 256>>>(nbr);
    gemm2_mma_kernel<<<NE / 128, 512>>>(b2);
    gemm3_mma_kernel<<<NE / 128, 256>>>(nbr, b3, f_y, out);
}

// round 13
// speedup vs baseline: 1.3368x; 1.1605x over previous
#include <cuda_runtime.h>
#include <cuda_fp16.h>
#include <math.h>
#include <stdint.h>

#define N_Y   100000
#define N_X   20000
#define KNN   16
#define NE    (N_X * KNN)      // 320000 edges
#define HID   256
#define CIN   64

// Scratch (device globals: allocation-free contract)
__device__ __half  g_Ayh[(size_t)N_Y * HID];   // 51.2 MB (L2-resident)
__device__ __half  g_Bxh[(size_t)N_X * HID];   // 10.2 MB
__device__ __half  g_H1h[(size_t)NE * HID];    // 164 MB
__device__ __half  g_H2h[(size_t)NE * HID];    // 164 MB
// transposed + fp16-converted weights, [n][k] dense
__device__ __half  g_W1aT[256 * 192];
__device__ __half  g_W1bT[256 * 192];
__device__ __half  g_W2T[256 * 256];
__device__ __half  g_W3T[64 * 256];

// exact-erf gelu (kept for reference paths that don't need speed)
__device__ __forceinline__ float gelu_erf(float v) {
    return 0.5f * v * (1.0f + erff(v * 0.70710678118654752f));
}
// fast gelu: tanh form with HW tanh.approx.f32
__device__ __forceinline__ float gelu_f(float v) {
    float arg = 0.7978845608028654f * fmaf(0.044715f * v * v, v, v);
    float th;
    asm("tanh.approx.f32 %0, %1;" : "=f"(th) : "f"(arg));
    return 0.5f * v * (1.0f + th);
}
__device__ __forceinline__ uint32_t pack_h2(float lo, float hi) {
    __half2 h = __floats2half2_rn(lo, hi);
    return *reinterpret_cast<uint32_t*>(&h);
}
__device__ __forceinline__ void mma_f16(float* d, const uint32_t* a, const uint32_t* b) {
    asm volatile(
        "mma.sync.aligned.m16n8k16.row.col.f32.f16.f16.f32 "
        "{%0,%1,%2,%3}, {%4,%5,%6,%7}, {%8,%9}, {%0,%1,%2,%3};\n"
        : "+f"(d[0]), "+f"(d[1]), "+f"(d[2]), "+f"(d[3])
        : "r"(a[0]), "r"(a[1]), "r"(a[2]), "r"(a[3]), "r"(b[0]), "r"(b[1]));
}
__device__ __forceinline__ void ldsm_x4(uint32_t* r, uint32_t saddr) {
    asm volatile("ldmatrix.sync.aligned.m8n8.x4.shared.b16 {%0,%1,%2,%3}, [%4];"
                 : "=r"(r[0]), "=r"(r[1]), "=r"(r[2]), "=r"(r[3]) : "r"(saddr));
}
__device__ __forceinline__ uint32_t smem_u32(const void* p) {
    return (uint32_t)__cvta_generic_to_shared(p);
}
__device__ __forceinline__ void cpa16(uint32_t dst, const void* src) {
    asm volatile("cp.async.ca.shared.global [%0], [%1], 16;\n" :: "r"(dst), "l"(src));
}
#define CPA_COMMIT asm volatile("cp.async.commit_group;\n")
#define CPA_WAIT0  asm volatile("cp.async.wait_group 0;\n")

// BK=32 fp16 tile: row = 32 halves = 64 B = 4 chunks of 16 B.
__device__ __forceinline__ uint32_t swb32(int r, int chalf) {   // chalf mult of 8
    return (uint32_t)(r * 64) + (uint32_t)((((chalf >> 3) ^ ((r >> 1) & 3)) << 4));
}
__device__ __forceinline__ uint32_t ldsmA32(uint32_t base, int m0, int kk, int lane) {
    int r = m0 + (lane & 15);
    int ch = (kk >> 3) + (lane >> 4);
    return base + (uint32_t)(r * 64) + (uint32_t)(((ch ^ ((r >> 1) & 3)) << 4));
}
__device__ __forceinline__ uint32_t ldsmB32(uint32_t base, int n0, int kk, int lane) {
    int r = n0 + (lane & 7) + ((lane >> 4) << 3);
    int ch = (kk >> 3) + ((lane >> 3) & 1);
    return base + (uint32_t)(r * 64) + (uint32_t)(((ch ^ ((r >> 1) & 3)) << 4));
}

// ---------------------------------------------------------------------------
// One-launch weight transpose + fp16 convert (fp32 [K][N] -> half [N][K])
// ---------------------------------------------------------------------------
__global__ void transpose_all_kernel(const float* __restrict__ W1,
                                     const float* __restrict__ W2,
                                     const float* __restrict__ W3)
{
    __shared__ float t[32][33];
    int id = blockIdx.x;
    const float* src; __half* dst; int K, N, local;
    if (id < 48)       { src = W1;             dst = g_W1aT; K = 192; N = 256; local = id; }
    else if (id < 96)  { src = W1 + 192 * 256; dst = g_W1bT; K = 192; N = 256; local = id - 48; }
    else if (id < 160) { src = W2;             dst = g_W2T;  K = 256; N = 256; local = id - 96; }
    else               { src = W3;             dst = g_W3T;  K = 256; N = 64;  local = id - 160; }
    int nbx = N / 32;
    int n0 = (local % nbx) * 32, k0 = (local / nbx) * 32;
    int tx = threadIdx.x, ty = threadIdx.y;
#pragma unroll
    for (int i = 0; i < 32; i += 8)
        t[ty + i][tx] = src[(size_t)(k0 + ty + i) * N + n0 + tx];
    __syncthreads();
#pragma unroll
    for (int i = 0; i < 32; i += 8)
        dst[(size_t)(n0 + ty + i) * K + k0 + tx] = __float2half(t[tx][ty + i]);
}

// ---------------------------------------------------------------------------
// Embed + GEMM1 (mma.sync fp16)
// ---------------------------------------------------------------------------
__global__ void __launch_bounds__(512) embed_mma_kernel(
    const float* __restrict__ pts,
    const float* __restrict__ bias,
    int which, int n)
{
    __shared__ __align__(128) char sA[2 * 128 * 64];
    __shared__ __align__(128) char sB[2 * 256 * 64];

    const __half* WT = which ? g_W1bT : g_W1aT;
    __half* dst = which ? g_Bxh : g_Ayh;
    const int tid  = threadIdx.x;
    const int row0 = blockIdx.x * 128;
    const int warp = tid >> 5, lane = tid & 31;
    const int wm = (warp & 3) * 32, wn = (warp >> 2) * 64;
    const int lr = lane >> 2, lc = lane & 3;
    const uint32_t sAu = smem_u32(sA), sBu = smem_u32(sB);

    uint32_t aOff[2][2], bOff[2][4];
#pragma unroll
    for (int kki = 0; kki < 2; kki++) {
#pragma unroll
        for (int mi = 0; mi < 2; mi++)
            aOff[kki][mi] = ldsmA32(0, wm + mi * 16, kki * 16, lane);
#pragma unroll
        for (int np = 0; np < 4; np++)
            bOff[kki][np] = ldsmB32(0, wn + np * 16, kki * 16, lane);
    }

    const int ar = tid >> 2, cb = (tid & 3) * 8;
    const int arow = row0 + ar;
    float3 p = make_float3(0.f, 0.f, 0.f);
    if (arow < n) { p.x = pts[arow * 3]; p.y = pts[arow * 3 + 1]; p.z = pts[arow * 3 + 2]; }
    const int bn = tid >> 1, bw = (tid & 1) * 16;

    auto storeA = [&](int pbuf, int k0) {
        int e0e = k0 + cb;
        int c = e0e >> 6;
        float pc = c == 0 ? p.x : (c == 1 ? p.y : p.z);
        int fb = (e0e & 63) >> 1;
        uint32_t w[4];
#pragma unroll
        for (int i = 0; i < 4; i++) {
            float freq = exp2f(-0.41524101186f * (float)(fb + i));
            float s, cf;
            sincosf(pc * freq, &s, &cf);
            w[i] = pack_h2(s, cf);
        }
        *(uint4*)(sA + pbuf * 8192 + swb32(ar, cb)) = make_uint4(w[0], w[1], w[2], w[3]);
    };
    auto stageB = [&](int k0, int pbuf) {
        char* base = sB + pbuf * 16384;
        cpa16(smem_u32(base + swb32(bn, bw)),     WT + (size_t)bn * 192 + k0 + bw);
        cpa16(smem_u32(base + swb32(bn, bw + 8)), WT + (size_t)bn * 192 + k0 + bw + 8);
        CPA_COMMIT;
    };

    float acc[2][8][4];
#pragma unroll
    for (int mi = 0; mi < 2; mi++)
#pragma unroll
        for (int ni = 0; ni < 8; ni++)
#pragma unroll
            for (int t = 0; t < 4; t++) acc[mi][ni][t] = 0.f;

    storeA(0, 0);
    stageB(0, 0);

    const int NCH = 6;
    for (int i = 0; i < NCH; i++) {
        const int pb = i & 1;
        CPA_WAIT0;
        __syncthreads();
        if (i + 1 < NCH) stageB((i + 1) * 32, 1 - pb);
        const uint32_t aBase = sAu + pb * 8192, bBase = sBu + pb * 16384;
#pragma unroll
        for (int kki = 0; kki < 2; kki++) {
            uint32_t afr[2][4], bfr[4][4];
#pragma unroll
            for (int mi = 0; mi < 2; mi++)
                ldsm_x4(afr[mi], aBase + aOff[kki][mi]);
#pragma unroll
            for (int np = 0; np < 4; np++)
                ldsm_x4(bfr[np], bBase + bOff[kki][np]);
#pragma unroll
            for (int mi = 0; mi < 2; mi++)
#pragma unroll
                for (int np = 0; np < 4; np++) {
                    mma_f16(acc[mi][np * 2],     afr[mi], bfr[np]);
                    mma_f16(acc[mi][np * 2 + 1], afr[mi], bfr[np] + 2);
                }
        }
        if (i + 1 < NCH) storeA(1 - pb, (i + 1) * 32);
    }

#pragma unroll
    for (int mi = 0; mi < 2; mi++) {
        int r0 = row0 + wm + mi * 16 + lr;
        int r1 = r0 + 8;
#pragma unroll
        for (int ni = 0; ni < 8; ni++) {
            int col = wn + ni * 8 + lc * 2;
            float bb0 = bias ? bias[col]     : 0.f;
            float bb1 = bias ? bias[col + 1] : 0.f;
            if (r0 < n)
                *(uint32_t*)(dst + (size_t)r0 * 256 + col) =
                    pack_h2(acc[mi][ni][0] + bb0, acc[mi][ni][1] + bb1);
            if (r1 < n)
                *(uint32_t*)(dst + (size_t)r1 * 256 + col) =
                    pack_h2(acc[mi][ni][2] + bb0, acc[mi][ni][3] + bb1);
        }
    }
}

// ---------------------------------------------------------------------------
// H1 elementwise: H1h[e,:] = fp16(gelu(Ayh[nbr[e],:] + Bxh[e>>4,:]))
// 16 halves/thread; HADD2 adds; tanh.approx gelu.
// grid*block == NE*16 exactly.
// ---------------------------------------------------------------------------
__global__ void __launch_bounds__(256) h1_kernel(const int* __restrict__ nbr)
{
    int idx = blockIdx.x * 256 + threadIdx.x;   // [0, NE*16)
    int e   = idx >> 4;
    int c16 = (idx & 15) * 16;
    int nb  = __ldg(nbr + e);
    int q   = e >> 4;
    const __half* pA = g_Ayh + (size_t)nb * 256 + c16;
    const __half* pB = g_Bxh + (size_t)q  * 256 + c16;
#pragma unroll
    for (int half = 0; half < 2; half++) {
        uint4 aq = *(const uint4*)(pA + half * 8);
        uint4 bq = *(const uint4*)(pB + half * 8);
        const __half2* ah = (const __half2*)&aq;
        const __half2* bh = (const __half2*)&bq;
        uint32_t w[4];
#pragma unroll
        for (int t = 0; t < 4; t++) {
            float2 s = __half22float2(__hadd2(ah[t], bh[t]));
            w[t] = pack_h2(gelu_f(s.x), gelu_f(s.y));
        }
        *(uint4*)(g_H1h + (size_t)e * 256 + c16 + half * 8) =
            make_uint4(w[0], w[1], w[2], w[3]);
    }
}

// ---------------------------------------------------------------------------
// GEMM2 (pure): H2h = h(gelu( H1h @ W2 + b2 ))
// BM=128, BN=256, K=256, BK=32, 2-stage, all-cp.async staging.
// ---------------------------------------------------------------------------
__global__ void __launch_bounds__(512) gemm2_mma_kernel(const float* __restrict__ b2)
{
    __shared__ __align__(128) char sA[2 * 128 * 64];
    __shared__ __align__(128) char sB[2 * 256 * 64];

    const int tid  = threadIdx.x;
    const int e0   = blockIdx.x * 128;
    const int warp = tid >> 5, lane = tid & 31;
    const int wm = (warp & 3) * 32, wn = (warp >> 2) * 64;
    const int lr = lane >> 2, lc = lane & 3;
    const uint32_t sAu = smem_u32(sA), sBu = smem_u32(sB);

    uint32_t aOff[2][2], bOff[2][4];
#pragma unroll
    for (int kki = 0; kki < 2; kki++) {
#pragma unroll
        for (int mi = 0; mi < 2; mi++)
            aOff[kki][mi] = ldsmA32(0, wm + mi * 16, kki * 16, lane);
#pragma unroll
        for (int np = 0; np < 4; np++)
            bOff[kki][np] = ldsmB32(0, wn + np * 16, kki * 16, lane);
    }

    const int ar = tid >> 2, ac = (tid & 3) * 8;
    const __half* pH1 = g_H1h + (size_t)(e0 + ar) * 256 + ac;
    const int bn = tid >> 1, bw = (tid & 1) * 16;
    const __half* pW = g_W2T + (size_t)bn * 256;

    auto stage = [&](int k0, int pbuf) {
        cpa16(smem_u32(sA + pbuf * 8192 + swb32(ar, ac)), pH1 + k0);
        char* base = sB + pbuf * 16384;
        cpa16(smem_u32(base + swb32(bn, bw)),     pW + k0 + bw);
        cpa16(smem_u32(base + swb32(bn, bw + 8)), pW + k0 + bw + 8);
        CPA_COMMIT;
    };

    float acc[2][8][4];
#pragma unroll
    for (int mi = 0; mi < 2; mi++)
#pragma unroll
        for (int ni = 0; ni < 8; ni++)
#pragma unroll
            for (int t = 0; t < 4; t++) acc[mi][ni][t] = 0.f;

    stage(0, 0);

    const int NCH = 8;
    for (int i = 0; i < NCH; i++) {
        const int pb = i & 1;
        CPA_WAIT0;
        __syncthreads();
        if (i + 1 < NCH) stage((i + 1) * 32, 1 - pb);
        const uint32_t aBase = sAu + pb * 8192, bBase = sBu + pb * 16384;
#pragma unroll
        for (int kki = 0; kki < 2; kki++) {
            uint32_t afr[2][4], bfr[4][4];
#pragma unroll
            for (int mi = 0; mi < 2; mi++)
                ldsm_x4(afr[mi], aBase + aOff[kki][mi]);
#pragma unroll
            for (int np = 0; np < 4; np++)
                ldsm_x4(bfr[np], bBase + bOff[kki][np]);
#pragma unroll
            for (int mi = 0; mi < 2; mi++)
#pragma unroll
                for (int np = 0; np < 4; np++) {
                    mma_f16(acc[mi][np * 2],     afr[mi], bfr[np]);
                    mma_f16(acc[mi][np * 2 + 1], afr[mi], bfr[np] + 2);
                }
        }
    }

    // epilogue: +b2, fast gelu, fp16-store
#pragma unroll
    for (int mi = 0; mi < 2; mi++) {
        int r0 = e0 + wm + mi * 16 + lr;
#pragma unroll
        for (int ni = 0; ni < 8; ni++) {
            int col = wn + ni * 8 + lc * 2;
            float bb0 = b2[col], bb1 = b2[col + 1];
            *(uint32_t*)(g_H2h + (size_t)r0 * 256 + col) =
                pack_h2(gelu_f(acc[mi][ni][0] + bb0), gelu_f(acc[mi][ni][1] + bb1));
            *(uint32_t*)(g_H2h + (size_t)(r0 + 8) * 256 + col) =
                pack_h2(gelu_f(acc[mi][ni][2] + bb0), gelu_f(acc[mi][ni][3] + bb1));
        }
    }
}

// ---------------------------------------------------------------------------
// GEMM3 + segsum: out = segsum( (H2 @ W3 + b3) * f_y[nbr] )
// ---------------------------------------------------------------------------
__global__ void __launch_bounds__(256) gemm3_mma_kernel(
    const int*   __restrict__ nbr,
    const float* __restrict__ b3,
    const float* __restrict__ fy,
    float*       __restrict__ out)
{
    __shared__ __align__(128) char sA[2 * 128 * 64];
    __shared__ __align__(128) char sB3[2 * 64 * 64];
    __shared__ int s_nbr[128];

    const int tid  = threadIdx.x;
    const int e0   = blockIdx.x * 128;
    const int warp = tid >> 5, lane = tid & 31;
    const int lr = lane >> 2, lc = lane & 3;
    const uint32_t sAu = smem_u32(sA), sBu = smem_u32(sB3);

    if (tid < 128) s_nbr[tid] = nbr[e0 + tid];

    const int ar = tid >> 1, cw = (tid & 1) * 16;
    const __half* pA = g_H2h + (size_t)(e0 + ar) * 256 + cw;
    const int b3n = tid >> 2, b3w = (tid & 3) * 8;

    uint32_t aOff[2], bOff[2][4];
#pragma unroll
    for (int kki = 0; kki < 2; kki++) {
        aOff[kki] = ldsmA32(0, warp * 16, kki * 16, lane);
#pragma unroll
        for (int np = 0; np < 4; np++)
            bOff[kki][np] = ldsmB32(0, np * 16, kki * 16, lane);
    }

    auto stage = [&](int k0, int pbuf) {
        char* abase = sA + pbuf * 8192;
        cpa16(smem_u32(abase + swb32(ar, cw)),     pA + k0);
        cpa16(smem_u32(abase + swb32(ar, cw + 8)), pA + k0 + 8);
        cpa16(smem_u32(sB3 + pbuf * 4096 + swb32(b3n, b3w)),
              g_W3T + (size_t)b3n * 256 + k0 + b3w);
        CPA_COMMIT;
    };

    float acc3[8][4];
#pragma unroll
    for (int ni = 0; ni < 8; ni++)
#pragma unroll
        for (int t = 0; t < 4; t++) acc3[ni][t] = 0.f;

    stage(0, 0);

    const int NCH = 8;
    for (int i = 0; i < NCH; i++) {
        const int pb = i & 1;
        CPA_WAIT0;
        __syncthreads();
        if (i + 1 < NCH) stage((i + 1) * 32, 1 - pb);
        const uint32_t aBase = sAu + pb * 8192, bBase = sBu + pb * 4096;
#pragma unroll
        for (int kki = 0; kki < 2; kki++) {
            uint32_t afr[4], bfr[4][4];
            ldsm_x4(afr, aBase + aOff[kki]);
#pragma unroll
            for (int np = 0; np < 4; np++)
                ldsm_x4(bfr[np], bBase + bOff[kki][np]);
#pragma unroll
            for (int np = 0; np < 4; np++) {
                mma_f16(acc3[np * 2],     afr, bfr[np]);
                mma_f16(acc3[np * 2 + 1], afr, bfr[np] + 2);
            }
        }
    }

    {
        int r0 = warp * 16 + lr;
        int nb0 = s_nbr[r0], nb1 = s_nbr[r0 + 8];
        const int q = blockIdx.x * 8 + warp;
#pragma unroll
        for (int ni = 0; ni < 8; ni++) {
            int col = ni * 8 + lc * 2;
            float bb0 = b3[col], bb1 = b3[col + 1];
            float2 f0 = *(const float2*)(fy + (size_t)nb0 * 64 + col);
            float2 f1 = *(const float2*)(fy + (size_t)nb1 * 64 + col);
            float s0 = (acc3[ni][0] + bb0) * f0.x + (acc3[ni][2] + bb0) * f1.x;
            float s1 = (acc3[ni][1] + bb1) * f0.y + (acc3[ni][3] + bb1) * f1.y;
#pragma unroll
            for (int off = 4; off <= 16; off <<= 1) {
                s0 += __shfl_xor_sync(0xFFFFFFFFu, s0, off);
                s1 += __shfl_xor_sync(0xFFFFFFFFu, s1, off);
            }
            if (lr == 0)
                *(float2*)(out + (size_t)q * 64 + col) = make_float2(s0, s1);
        }
    }
}

// ---------------------------------------------------------------------------
extern "C" void kernel_launch(void* const* d_in, const int* in_sizes, int n_in,
                              void* d_out, int out_size)
{
    const float* y   = (const float*)d_in[0];
    const float* x   = (const float*)d_in[1];
    const float* f_y = (const float*)d_in[2];
    const int*   nbr = (const int*)d_in[3];
    // d_in[4] = neighbors_row_splits (uniform K=16 -> q = e>>4)
    const float* W1  = (const float*)d_in[5];
    const float* b1  = (const float*)d_in[6];
    const float* W2  = (const float*)d_in[7];
    const float* b2  = (const float*)d_in[8];
    const float* W3  = (const float*)d_in[9];
    const float* b3  = (const float*)d_in[10];
    float* out = (float*)d_out;

    transpose_all_kernel<<<176, dim3(32, 8)>>>(W1, W2, W3);
    embed_mma_kernel<<<(N_Y + 127) / 128, 512>>>(y, nullptr, 0, N_Y);
    embed_mma_kernel<<<(N_X + 127) / 128, 512>>>(x, b1, 1, N_X);
    h1_kernel<<<(NE * 16) / 256, 256>>>(nbr);
    gemm2_mma_kernel<<<NE / 128, 512>>>(b2);
    gemm3_mma_kernel<<<NE / 128, 256>>>(nbr, b3, f_y, out);
}